// round 7
// baseline (speedup 1.0000x reference)
#include <cuda_runtime.h>
#include <cstdint>

// ---------------------------------------------------------------------------
// MoE grouped GEMM: Y[t,o] = sum_k X[t,k] * W[e(t),o,k]
//   X: [1048576,128] f32, W: [16,128,128] f32, expert_size: [16] (i32 OR i64).
// compute_103 PTX target (no tcgen05) -> legacy mma.sync m16n8k8 tf32 path.
// Each CTA: loads W_e once into SMEM, streams 128-row X tiles with cp.async
// double buffering. 256 threads, 8 warps, warp-tile 16x128.
// ---------------------------------------------------------------------------

#define TM   128          // tile rows (M)
#define KD   128          // K
#define ND   128          // N
#define KP   132          // padded SMEM row stride (floats) -> conflict-free
#define CPE  64           // CTAs per expert
#define NEXP 16

static constexpr int SMEM_FLOATS = ND * KP + 2 * TM * KP;   // 50688 floats = 202752 B

__device__ __forceinline__ uint32_t smem_u32(const void* p) {
    uint32_t a;
    asm("{ .reg .u64 t; cvta.to.shared.u64 t, %1; cvt.u32.u64 %0, t; }" : "=r"(a) : "l"(p));
    return a;
}

__device__ __forceinline__ uint32_t f2tf32(float v) {
    uint32_t r;
    asm("cvt.rn.tf32.f32 %0, %1;" : "=r"(r) : "f"(v));
    return r;
}

__device__ __forceinline__ void cp16(uint32_t dst, const void* src) {
    asm volatile("cp.async.cg.shared.global [%0], [%1], 16;" :: "r"(dst), "l"(src));
}

__device__ __forceinline__ void mma_tf32(float c[4], uint32_t a0, uint32_t a1,
                                         uint32_t a2, uint32_t a3,
                                         uint32_t b0, uint32_t b1) {
    asm volatile(
        "mma.sync.aligned.m16n8k8.row.col.f32.tf32.tf32.f32 "
        "{%0,%1,%2,%3}, {%4,%5,%6,%7}, {%8,%9}, {%0,%1,%2,%3};"
        : "+f"(c[0]), "+f"(c[1]), "+f"(c[2]), "+f"(c[3])
        : "r"(a0), "r"(a1), "r"(a2), "r"(a3), "r"(b0), "r"(b1));
}

// expert_size may be int64 (as declared) or int32 (JAX x64-disabled downcast).
// Sniff: first 8 bytes as i64; a sane value fits in [0, total_tokens].
__device__ __forceinline__ long long esz_get(const void* esz, int i, bool is64) {
    if (is64) return reinterpret_cast<const long long*>(esz)[i];
    return (long long)reinterpret_cast<const int*>(esz)[i];
}

__global__ void __launch_bounds__(256, 1)
moe_mma_kernel(const float* __restrict__ X,
               const float* __restrict__ W,
               const void* __restrict__ expert_size,
               float* __restrict__ Y,
               long long total_tokens)
{
    extern __shared__ float smem[];
    float* Bs = smem;                       // [ND][KP]
    float* As = smem + ND * KP;             // 2 x [TM][KP]
    const uint32_t As_u32 = smem_u32(As);

    const int tid  = threadIdx.x;
    const int wid  = tid >> 5;
    const int lane = tid & 31;
    const int g    = lane >> 2;             // 0..7
    const int tig  = lane & 3;              // 0..3

    const int e    = blockIdx.x / CPE;
    const int slot = blockIdx.x % CPE;

    // Detect expert_size dtype, then prefix-scan for this expert's row base.
    const long long probe = reinterpret_cast<const long long*>(expert_size)[0];
    const bool is64 = (probe >= 0 && probe <= total_tokens);

    long long rb = 0;
    for (int i = 0; i < e; i++) rb += esz_get(expert_size, i, is64);
    long long esize = esz_get(expert_size, e, is64);

    // Defensive clamps: never form an out-of-range address even if the dtype
    // sniff is wrong (wrong output beats an illegal-access fault for debug).
    if (rb < 0) rb = 0;
    if (rb > total_tokens) rb = total_tokens;
    if (esize < 0) esize = 0;
    if (rb + esize > total_tokens) esize = total_tokens - rb;

    const int etiles = (int)(esize / TM);
    const int q0 = etiles / CPE, r0c = etiles % CPE;
    const int tpc = q0 + (slot < r0c ? 1 : 0);
    const int t0  = slot * q0 + (slot < r0c ? slot : r0c);
    if (tpc == 0) return;

    // ---- Load W_e into SMEM (tf32 RN converted), padded stride KP ----
    {
        const float4* wp = reinterpret_cast<const float4*>(W + (size_t)e * ND * KD);
        for (int q = tid; q < ND * KD / 4; q += 256) {
            int r = q >> 5, c4 = (q & 31) << 2;
            float4 v = wp[q];
            uint32_t c0 = f2tf32(v.x), c1 = f2tf32(v.y), c2 = f2tf32(v.z), c3 = f2tf32(v.w);
            uint32_t a = smem_u32(Bs) + (uint32_t)(r * KP + c4) * 4u;
            asm volatile("st.shared.v4.b32 [%0], {%1,%2,%3,%4};"
                         :: "r"(a), "r"(c0), "r"(c1), "r"(c2), "r"(c3) : "memory");
        }
    }

    // ---- Prefetch first X tile into buffer 0 ----
    {
        const float4* xp = reinterpret_cast<const float4*>(X + (rb + (long long)t0 * TM) * KD);
        for (int q = tid; q < TM * KD / 4; q += 256) {
            int r = q >> 5, c4 = (q & 31) << 2;
            cp16(As_u32 + (uint32_t)(r * KP + c4) * 4u, xp + q);
        }
        asm volatile("cp.async.commit_group;" ::: "memory");
    }

    const int warp_r0 = wid * 16 + g;       // this thread's first output row in tile

    for (int it = 0; it < tpc; it++) {
        const int buf = it & 1;

        // Prefetch next tile into the other buffer (empty group on last iter).
        if (it + 1 < tpc) {
            const float4* xp = reinterpret_cast<const float4*>(
                X + (rb + (long long)(t0 + it + 1) * TM) * KD);
            uint32_t dbase = As_u32 + (uint32_t)((buf ^ 1) * TM * KP) * 4u;
            for (int q = tid; q < TM * KD / 4; q += 256) {
                int r = q >> 5, c4 = (q & 31) << 2;
                cp16(dbase + (uint32_t)(r * KP + c4) * 4u, xp + q);
            }
        }
        asm volatile("cp.async.commit_group;" ::: "memory");
        asm volatile("cp.async.wait_group 1;" ::: "memory");
        __syncthreads();

        // ---- Compute: warp-tile 16 x 128, m16n8k8 tf32 ----
        const float* A0 = As + buf * TM * KP;
        float acc[16][4];
        #pragma unroll
        for (int nb = 0; nb < 16; nb++)
            #pragma unroll
            for (int i = 0; i < 4; i++) acc[nb][i] = 0.0f;

        #pragma unroll 4
        for (int ks = 0; ks < 16; ks++) {
            const int k = ks * 8;
            uint32_t a0 = f2tf32(A0[(warp_r0)     * KP + k + tig]);
            uint32_t a1 = f2tf32(A0[(warp_r0 + 8) * KP + k + tig]);
            uint32_t a2 = f2tf32(A0[(warp_r0)     * KP + k + tig + 4]);
            uint32_t a3 = f2tf32(A0[(warp_r0 + 8) * KP + k + tig + 4]);
            #pragma unroll
            for (int nb = 0; nb < 16; nb++) {
                uint32_t b0 = __float_as_uint(Bs[(nb * 8 + g) * KP + k + tig]);
                uint32_t b1 = __float_as_uint(Bs[(nb * 8 + g) * KP + k + tig + 4]);
                mma_tf32(acc[nb], a0, a1, a2, a3, b0, b1);
            }
        }

        // ---- Epilogue: st.global.v2 (full 32B sectors per 4-lane group) ----
        {
            const long long tile_row = rb + (long long)(t0 + it) * TM;
            float* dst0 = Y + (tile_row + warp_r0)     * ND + tig * 2;
            float* dst1 = Y + (tile_row + warp_r0 + 8) * ND + tig * 2;
            #pragma unroll
            for (int nb = 0; nb < 16; nb++) {
                float2 v0 = make_float2(acc[nb][0], acc[nb][1]);
                float2 v1 = make_float2(acc[nb][2], acc[nb][3]);
                *reinterpret_cast<float2*>(dst0 + nb * 8) = v0;
                *reinterpret_cast<float2*>(dst1 + nb * 8) = v1;
            }
        }
        __syncthreads();
    }
}

extern "C" void kernel_launch(void* const* d_in, const int* in_sizes, int n_in,
                              void* d_out, int out_size) {
    const float* X   = (const float*)d_in[0];
    const float* W   = (const float*)d_in[1];
    const void*  esz = d_in[2];
    float*       Y   = (float*)d_out;

    const long long total_tokens = (long long)in_sizes[0] / KD;

    cudaFuncSetAttribute(moe_mma_kernel,
                         cudaFuncAttributeMaxDynamicSharedMemorySize,
                         SMEM_FLOATS * (int)sizeof(float));

    moe_mma_kernel<<<NEXP * CPE, 256, SMEM_FLOATS * (int)sizeof(float)>>>(
        X, W, esz, Y, total_tokens);
}

// round 11
// speedup vs baseline: 1.5182x; 1.5182x over previous
#include <cuda_runtime.h>
#include <cstdint>

// ---------------------------------------------------------------------------
// MoE grouped GEMM: Y[t,o] = sum_k X[t,k] * W[e(t),o,k]
//   X: [1048576,128] f32, W: [16,128,128] f32, expert_size: [16] (i32 OR i64).
// compute_103 PTX target (no tcgen05) -> legacy mma.sync m16n8k8 tf32 path.
// Each CTA: W_e resident in SMEM, streams 128-row X tiles with cp.async
// double buffering. 512 threads / 16 warps; warp-tile 16x64 (8M x 2N grid)
// for 4 warps per SMSP (latency hiding -- R7 profile showed issue=22.8%).
// ---------------------------------------------------------------------------

#define TM   128          // tile rows (M)
#define KD   128          // K
#define ND   128          // N
#define KP   132          // padded SMEM row stride (floats) -> conflict-free
#define CPE  64           // CTAs per expert
#define NEXP 16
#define NTHREADS 512

static constexpr int SMEM_FLOATS = ND * KP + 2 * TM * KP;   // 50688 floats = 202752 B

__device__ __forceinline__ uint32_t smem_u32(const void* p) {
    uint32_t a;
    asm("{ .reg .u64 t; cvta.to.shared.u64 t, %1; cvt.u32.u64 %0, t; }" : "=r"(a) : "l"(p));
    return a;
}

__device__ __forceinline__ uint32_t f2tf32(float v) {
    uint32_t r;
    asm("cvt.rn.tf32.f32 %0, %1;" : "=r"(r) : "f"(v));
    return r;
}

__device__ __forceinline__ void cp16(uint32_t dst, const void* src) {
    asm volatile("cp.async.cg.shared.global [%0], [%1], 16;" :: "r"(dst), "l"(src));
}

__device__ __forceinline__ void mma_tf32(float c[4], uint32_t a0, uint32_t a1,
                                         uint32_t a2, uint32_t a3,
                                         uint32_t b0, uint32_t b1) {
    asm volatile(
        "mma.sync.aligned.m16n8k8.row.col.f32.tf32.tf32.f32 "
        "{%0,%1,%2,%3}, {%4,%5,%6,%7}, {%8,%9}, {%0,%1,%2,%3};"
        : "+f"(c[0]), "+f"(c[1]), "+f"(c[2]), "+f"(c[3])
        : "r"(a0), "r"(a1), "r"(a2), "r"(a3), "r"(b0), "r"(b1));
}

// expert_size may be int64 (as declared) or int32 (JAX x64-disabled downcast).
__device__ __forceinline__ long long esz_get(const void* esz, int i, bool is64) {
    if (is64) return reinterpret_cast<const long long*>(esz)[i];
    return (long long)reinterpret_cast<const int*>(esz)[i];
}

__global__ void __launch_bounds__(NTHREADS, 1)
moe_mma_kernel(const float* __restrict__ X,
               const float* __restrict__ W,
               const void* __restrict__ expert_size,
               float* __restrict__ Y,
               long long total_tokens)
{
    extern __shared__ float smem[];
    float* Bs = smem;                       // [ND][KP]
    float* As = smem + ND * KP;             // 2 x [TM][KP]
    const uint32_t As_u32 = smem_u32(As);

    const int tid  = threadIdx.x;
    const int wid  = tid >> 5;
    const int lane = tid & 31;
    const int g    = lane >> 2;             // 0..7
    const int tig  = lane & 3;              // 0..3

    const int wm   = wid >> 1;              // 0..7  (M position, 16 rows each)
    const int wn   = wid & 1;               // 0..1  (N half, 64 cols each)

    const int e    = blockIdx.x / CPE;
    const int slot = blockIdx.x % CPE;

    // Detect expert_size dtype, then prefix-scan for this expert's row base.
    const long long probe = reinterpret_cast<const long long*>(expert_size)[0];
    const bool is64 = (probe >= 0 && probe <= total_tokens);

    long long rb = 0;
    for (int i = 0; i < e; i++) rb += esz_get(expert_size, i, is64);
    long long esize = esz_get(expert_size, e, is64);

    // Defensive clamps: never form an out-of-range address.
    if (rb < 0) rb = 0;
    if (rb > total_tokens) rb = total_tokens;
    if (esize < 0) esize = 0;
    if (rb + esize > total_tokens) esize = total_tokens - rb;

    const int etiles = (int)(esize / TM);
    const int q0 = etiles / CPE, r0c = etiles % CPE;
    const int tpc = q0 + (slot < r0c ? 1 : 0);
    const int t0  = slot * q0 + (slot < r0c ? slot : r0c);
    if (tpc == 0) return;

    // ---- Load W_e into SMEM (tf32 RN converted), padded stride KP ----
    {
        const float4* wp = reinterpret_cast<const float4*>(W + (size_t)e * ND * KD);
        for (int q = tid; q < ND * KD / 4; q += NTHREADS) {
            int r = q >> 5, c4 = (q & 31) << 2;
            float4 v = wp[q];
            uint32_t c0 = f2tf32(v.x), c1 = f2tf32(v.y), c2 = f2tf32(v.z), c3 = f2tf32(v.w);
            uint32_t a = smem_u32(Bs) + (uint32_t)(r * KP + c4) * 4u;
            asm volatile("st.shared.v4.b32 [%0], {%1,%2,%3,%4};"
                         :: "r"(a), "r"(c0), "r"(c1), "r"(c2), "r"(c3) : "memory");
        }
    }

    // ---- Prefetch first X tile into buffer 0 ----
    {
        const float4* xp = reinterpret_cast<const float4*>(X + (rb + (long long)t0 * TM) * KD);
        for (int q = tid; q < TM * KD / 4; q += NTHREADS) {
            int r = q >> 5, c4 = (q & 31) << 2;
            cp16(As_u32 + (uint32_t)(r * KP + c4) * 4u, xp + q);
        }
        asm volatile("cp.async.commit_group;" ::: "memory");
    }

    const int row_a = wm * 16 + g;          // this thread's first A row in tile
    const int colb0 = wn * 64;              // this warp's first output column

    for (int it = 0; it < tpc; it++) {
        const int buf = it & 1;

        // Prefetch next tile into the other buffer (empty group on last iter).
        if (it + 1 < tpc) {
            const float4* xp = reinterpret_cast<const float4*>(
                X + (rb + (long long)(t0 + it + 1) * TM) * KD);
            uint32_t dbase = As_u32 + (uint32_t)((buf ^ 1) * TM * KP) * 4u;
            for (int q = tid; q < TM * KD / 4; q += NTHREADS) {
                int r = q >> 5, c4 = (q & 31) << 2;
                cp16(dbase + (uint32_t)(r * KP + c4) * 4u, xp + q);
            }
        }
        asm volatile("cp.async.commit_group;" ::: "memory");
        asm volatile("cp.async.wait_group 1;" ::: "memory");
        __syncthreads();

        // ---- Compute: warp-tile 16 x 64, m16n8k8 tf32 ----
        const float* A0 = As + buf * TM * KP;
        float acc[8][4];
        #pragma unroll
        for (int nb = 0; nb < 8; nb++)
            #pragma unroll
            for (int i = 0; i < 4; i++) acc[nb][i] = 0.0f;

        #pragma unroll
        for (int ks = 0; ks < 16; ks++) {
            const int k = ks * 8;
            uint32_t a0 = f2tf32(A0[(row_a)     * KP + k + tig]);
            uint32_t a1 = f2tf32(A0[(row_a + 8) * KP + k + tig]);
            uint32_t a2 = f2tf32(A0[(row_a)     * KP + k + tig + 4]);
            uint32_t a3 = f2tf32(A0[(row_a + 8) * KP + k + tig + 4]);
            #pragma unroll
            for (int nb = 0; nb < 8; nb++) {
                uint32_t b0 = __float_as_uint(Bs[(colb0 + nb * 8 + g) * KP + k + tig]);
                uint32_t b1 = __float_as_uint(Bs[(colb0 + nb * 8 + g) * KP + k + tig + 4]);
                mma_tf32(acc[nb], a0, a1, a2, a3, b0, b1);
            }
        }

        // ---- Epilogue: st.global.v2 (full 32B sectors per 4-lane group) ----
        {
            const long long tile_row = rb + (long long)(t0 + it) * TM;
            float* dst0 = Y + (tile_row + row_a)     * ND + colb0 + tig * 2;
            float* dst1 = Y + (tile_row + row_a + 8) * ND + colb0 + tig * 2;
            #pragma unroll
            for (int nb = 0; nb < 8; nb++) {
                float2 v0 = make_float2(acc[nb][0], acc[nb][1]);
                float2 v1 = make_float2(acc[nb][2], acc[nb][3]);
                *reinterpret_cast<float2*>(dst0 + nb * 8) = v0;
                *reinterpret_cast<float2*>(dst1 + nb * 8) = v1;
            }
        }
        __syncthreads();
    }
}

extern "C" void kernel_launch(void* const* d_in, const int* in_sizes, int n_in,
                              void* d_out, int out_size) {
    const float* X   = (const float*)d_in[0];
    const float* W   = (const float*)d_in[1];
    const void*  esz = d_in[2];
    float*       Y   = (float*)d_out;

    const long long total_tokens = (long long)in_sizes[0] / KD;

    cudaFuncSetAttribute(moe_mma_kernel,
                         cudaFuncAttributeMaxDynamicSharedMemorySize,
                         SMEM_FLOATS * (int)sizeof(float));

    moe_mma_kernel<<<NEXP * CPE, NTHREADS, SMEM_FLOATS * (int)sizeof(float)>>>(
        X, W, esz, Y, total_tokens);
}

// round 13
// speedup vs baseline: 1.6153x; 1.0640x over previous
#include <cuda_runtime.h>
#include <cstdint>

// ---------------------------------------------------------------------------
// MoE grouped GEMM: Y[t,o] = sum_k X[t,k] * W[e(t),o,k]
//   X: [1048576,128] f32, W: [16,128,128] f32, expert_size: [16] (i32/i64).
// mma.sync m16n8k8 tf32. 256 threads / 8 warps, warp-tile 32x64 (1.5
// smem-words per mma). W stored in SMEM in mma-FRAGMENT order so B operands
// load as ld.shared.v4 (4 per ks instead of 16 scalar LDS). X tiles double
// buffered via cp.async. R11 profile: crossbar-bound (L1 66.6%) -> cut bytes.
// ---------------------------------------------------------------------------

#define TM   128          // tile rows (M)
#define KD   128          // K
#define ND   128          // N
#define KP   132          // padded A stride (floats) -> conflict-free scalar LDS
#define CPE  64           // CTAs per expert
#define NEXP 16
#define NTHREADS 256

// SMEM: Bfrag [2 wn][16 ks][4 chunk][32 lane] float4 = 64 KB, then A 2x128xKP.
static constexpr int BF_FLOATS   = 2 * 16 * 4 * 32 * 4;            // 16384
static constexpr int SMEM_FLOATS = BF_FLOATS + 2 * TM * KP;        // 50176 = 200704 B

__device__ __forceinline__ uint32_t smem_u32(const void* p) {
    uint32_t a;
    asm("{ .reg .u64 t; cvta.to.shared.u64 t, %1; cvt.u32.u64 %0, t; }" : "=r"(a) : "l"(p));
    return a;
}

__device__ __forceinline__ uint32_t f2tf32(float v) {
    uint32_t r;
    asm("cvt.rn.tf32.f32 %0, %1;" : "=r"(r) : "f"(v));
    return r;
}

__device__ __forceinline__ void cp16(uint32_t dst, const void* src) {
    asm volatile("cp.async.cg.shared.global [%0], [%1], 16;" :: "r"(dst), "l"(src));
}

__device__ __forceinline__ void mma_tf32(float c[4], uint32_t a0, uint32_t a1,
                                         uint32_t a2, uint32_t a3,
                                         uint32_t b0, uint32_t b1) {
    asm volatile(
        "mma.sync.aligned.m16n8k8.row.col.f32.tf32.tf32.f32 "
        "{%0,%1,%2,%3}, {%4,%5,%6,%7}, {%8,%9}, {%0,%1,%2,%3};"
        : "+f"(c[0]), "+f"(c[1]), "+f"(c[2]), "+f"(c[3])
        : "r"(a0), "r"(a1), "r"(a2), "r"(a3), "r"(b0), "r"(b1));
}

__device__ __forceinline__ long long esz_get(const void* esz, int i, bool is64) {
    if (is64) return reinterpret_cast<const long long*>(esz)[i];
    return (long long)reinterpret_cast<const int*>(esz)[i];
}

__global__ void __launch_bounds__(NTHREADS, 1)
moe_mma_kernel(const float* __restrict__ X,
               const float* __restrict__ W,
               const void* __restrict__ expert_size,
               float* __restrict__ Y,
               long long total_tokens)
{
    extern __shared__ float smem[];
    float* Bf = smem;                       // fragment-order W
    float* As = smem + BF_FLOATS;           // 2 x [TM][KP]
    const uint32_t Bf_u32 = smem_u32(Bf);
    const uint32_t As_u32 = smem_u32(As);

    const int tid  = threadIdx.x;
    const int wid  = tid >> 5;
    const int lane = tid & 31;
    const int g    = lane >> 2;             // 0..7
    const int tig  = lane & 3;              // 0..3

    const int wm   = wid >> 1;              // 0..3  (M position, 32 rows each)
    const int wn   = wid & 1;               // 0..1  (N half, 64 cols)

    const int e    = blockIdx.x / CPE;
    const int slot = blockIdx.x % CPE;

    // expert_size dtype sniff (declared i64; JAX x64-off delivers i32).
    const long long probe = reinterpret_cast<const long long*>(expert_size)[0];
    const bool is64 = (probe >= 0 && probe <= total_tokens);

    long long rb = 0;
    for (int i = 0; i < e; i++) rb += esz_get(expert_size, i, is64);
    long long esize = esz_get(expert_size, e, is64);
    if (rb < 0) rb = 0;
    if (rb > total_tokens) rb = total_tokens;
    if (esize < 0) esize = 0;
    if (rb + esize > total_tokens) esize = total_tokens - rb;

    const int etiles = (int)(esize / TM);
    const int q0 = etiles / CPE, r0c = etiles % CPE;
    const int tpc = q0 + (slot < r0c ? 1 : 0);
    const int t0  = slot * q0 + (slot < r0c ? slot : r0c);
    if (tpc == 0) return;

    // ---- Stage W_e into FRAGMENT-order SMEM (tf32 RN) ----
    // Entry (vwn, vks, c, l): float4 = {b0(nb=2c), b1(nb=2c), b0(nb=2c+1), b1(nb=2c+1)}
    // where for lane l: vg=l>>2, vtig=l&3, k=vks*8+vtig, col n = vwn*64 + nb*8 + vg,
    // b0 = W[n][k], b1 = W[n][k+4].  Layout is conflict-free for v4 loads.
    {
        const float* wp = W + (size_t)e * ND * KD;
        for (int q = tid; q < 2 * 16 * 4 * 32; q += NTHREADS) {
            int l   = q & 31;
            int c   = (q >> 5) & 3;
            int vks = (q >> 7) & 15;
            int vwn = q >> 11;
            int vg = l >> 2, vtig = l & 3;
            int k  = vks * 8 + vtig;
            int n0 = vwn * 64 + (2 * c) * 8 + vg;
            int n1 = n0 + 8;
            uint32_t f0 = f2tf32(wp[n0 * KD + k]);
            uint32_t f1 = f2tf32(wp[n0 * KD + k + 4]);
            uint32_t f2 = f2tf32(wp[n1 * KD + k]);
            uint32_t f3 = f2tf32(wp[n1 * KD + k + 4]);
            uint32_t a = Bf_u32 + (uint32_t)q * 16u;
            asm volatile("st.shared.v4.b32 [%0], {%1,%2,%3,%4};"
                         :: "r"(a), "r"(f0), "r"(f1), "r"(f2), "r"(f3) : "memory");
        }
    }

    // ---- Prefetch first X tile into buffer 0 ----
    {
        const float4* xp = reinterpret_cast<const float4*>(X + (rb + (long long)t0 * TM) * KD);
        for (int q = tid; q < TM * KD / 4; q += NTHREADS) {
            int r = q >> 5, c4 = (q & 31) << 2;
            cp16(As_u32 + (uint32_t)(r * KP + c4) * 4u, xp + q);
        }
        asm volatile("cp.async.commit_group;" ::: "memory");
    }

    const int row_a = wm * 32 + g;            // first A row (mc=0) for this thread
    const int colb0 = wn * 64;
    // Per-ks B base for this warp: region (wn*16 + ks) * 2048 B + lane*16.
    const uint32_t bf_warp = Bf_u32 + (uint32_t)(wn * 16) * 2048u + (uint32_t)lane * 16u;

    for (int it = 0; it < tpc; it++) {
        const int buf = it & 1;

        if (it + 1 < tpc) {
            const float4* xp = reinterpret_cast<const float4*>(
                X + (rb + (long long)(t0 + it + 1) * TM) * KD);
            uint32_t dbase = As_u32 + (uint32_t)((buf ^ 1) * TM * KP) * 4u;
            for (int q = tid; q < TM * KD / 4; q += NTHREADS) {
                int r = q >> 5, c4 = (q & 31) << 2;
                cp16(dbase + (uint32_t)(r * KP + c4) * 4u, xp + q);
            }
        }
        asm volatile("cp.async.commit_group;" ::: "memory");
        asm volatile("cp.async.wait_group 1;" ::: "memory");
        __syncthreads();

        // ---- Compute: warp-tile 32 x 64, m16n8k8 tf32 ----
        const float* A0 = As + buf * TM * KP;
        float acc[16][4];
        #pragma unroll
        for (int p = 0; p < 16; p++)
            #pragma unroll
            for (int i = 0; i < 4; i++) acc[p][i] = 0.0f;

        #pragma unroll 4
        for (int ks = 0; ks < 16; ks++) {
            const int k = ks * 8;
            // A fragments for two m16 chunks (rows row_a / row_a+16).
            uint32_t a0[2], a1[2], a2[2], a3[2];
            #pragma unroll
            for (int mc = 0; mc < 2; mc++) {
                const float* Ar = A0 + (row_a + mc * 16) * KP + k + tig;
                a0[mc] = f2tf32(Ar[0]);
                a1[mc] = f2tf32(Ar[8 * KP]);
                a2[mc] = f2tf32(Ar[4]);
                a3[mc] = f2tf32(Ar[8 * KP + 4]);
            }
            // B fragments: 4 x v4 (nb pairs), conflict-free.
            uint32_t b[16];
            const uint32_t bks = bf_warp + (uint32_t)ks * 2048u;
            #pragma unroll
            for (int c = 0; c < 4; c++) {
                asm volatile("ld.shared.v4.b32 {%0,%1,%2,%3}, [%4];"
                             : "=r"(b[c * 4 + 0]), "=r"(b[c * 4 + 1]),
                               "=r"(b[c * 4 + 2]), "=r"(b[c * 4 + 3])
                             : "r"(bks + (uint32_t)c * 512u));
            }
            #pragma unroll
            for (int mc = 0; mc < 2; mc++)
                #pragma unroll
                for (int nb = 0; nb < 8; nb++)
                    mma_tf32(acc[mc * 8 + nb], a0[mc], a1[mc], a2[mc], a3[mc],
                             b[nb * 2], b[nb * 2 + 1]);
        }

        // ---- Epilogue: st.global.v2 ----
        {
            const long long tile_row = rb + (long long)(t0 + it) * TM;
            #pragma unroll
            for (int mc = 0; mc < 2; mc++) {
                float* dst0 = Y + (tile_row + row_a + mc * 16)     * ND + colb0 + tig * 2;
                float* dst1 = Y + (tile_row + row_a + mc * 16 + 8) * ND + colb0 + tig * 2;
                #pragma unroll
                for (int nb = 0; nb < 8; nb++) {
                    float2 v0 = make_float2(acc[mc * 8 + nb][0], acc[mc * 8 + nb][1]);
                    float2 v1 = make_float2(acc[mc * 8 + nb][2], acc[mc * 8 + nb][3]);
                    *reinterpret_cast<float2*>(dst0 + nb * 8) = v0;
                    *reinterpret_cast<float2*>(dst1 + nb * 8) = v1;
                }
            }
        }
        __syncthreads();
    }
}

extern "C" void kernel_launch(void* const* d_in, const int* in_sizes, int n_in,
                              void* d_out, int out_size) {
    const float* X   = (const float*)d_in[0];
    const float* W   = (const float*)d_in[1];
    const void*  esz = d_in[2];
    float*       Y   = (float*)d_out;

    const long long total_tokens = (long long)in_sizes[0] / KD;

    cudaFuncSetAttribute(moe_mma_kernel,
                         cudaFuncAttributeMaxDynamicSharedMemorySize,
                         SMEM_FLOATS * (int)sizeof(float));

    moe_mma_kernel<<<NEXP * CPE, NTHREADS, SMEM_FLOATS * (int)sizeof(float)>>>(
        X, W, esz, Y, total_tokens);
}

// round 14
// speedup vs baseline: 1.6213x; 1.0037x over previous
#include <cuda_runtime.h>
#include <cstdint>

// ---------------------------------------------------------------------------
// MoE grouped GEMM: Y[t,o] = sum_k X[t,k] * W[e(t),o,k]
//   X: [1048576,128] f32, W: [16,128,128] f32, expert_size: [16] (i32/i64).
// mma.sync m16n8k8 tf32. 256 threads / 8 warps, warp-tile 32x64. W in
// fragment-order SMEM (B = 4x ld.shared.v4 per ks). X double-buffered via
// cp.async. R14: explicit REGISTER double-buffering of per-ks fragments +
// full unroll, so frag loads for ks+1 overlap the 16 mmas of ks (R13 showed
// additive tensor+LDS cycles -> latency exposure at ks boundaries).
// ---------------------------------------------------------------------------

#define TM   128
#define KD   128
#define ND   128
#define KP   132
#define CPE  64
#define NEXP 16
#define NTHREADS 256

static constexpr int BF_FLOATS   = 2 * 16 * 4 * 32 * 4;            // 16384
static constexpr int SMEM_FLOATS = BF_FLOATS + 2 * TM * KP;        // 200704 B

__device__ __forceinline__ uint32_t smem_u32(const void* p) {
    uint32_t a;
    asm("{ .reg .u64 t; cvta.to.shared.u64 t, %1; cvt.u32.u64 %0, t; }" : "=r"(a) : "l"(p));
    return a;
}

__device__ __forceinline__ uint32_t f2tf32(float v) {
    uint32_t r;
    asm("cvt.rn.tf32.f32 %0, %1;" : "=r"(r) : "f"(v));
    return r;
}

__device__ __forceinline__ void cp16(uint32_t dst, const void* src) {
    asm volatile("cp.async.cg.shared.global [%0], [%1], 16;" :: "r"(dst), "l"(src));
}

__device__ __forceinline__ void mma_tf32(float c[4], uint32_t a0, uint32_t a1,
                                         uint32_t a2, uint32_t a3,
                                         uint32_t b0, uint32_t b1) {
    asm volatile(
        "mma.sync.aligned.m16n8k8.row.col.f32.tf32.tf32.f32 "
        "{%0,%1,%2,%3}, {%4,%5,%6,%7}, {%8,%9}, {%0,%1,%2,%3};"
        : "+f"(c[0]), "+f"(c[1]), "+f"(c[2]), "+f"(c[3])
        : "r"(a0), "r"(a1), "r"(a2), "r"(a3), "r"(b0), "r"(b1));
}

__device__ __forceinline__ long long esz_get(const void* esz, int i, bool is64) {
    if (is64) return reinterpret_cast<const long long*>(esz)[i];
    return (long long)reinterpret_cast<const int*>(esz)[i];
}

// Load one ks worth of fragments into registers.
__device__ __forceinline__ void load_frags(const float* A0, uint32_t bf_warp,
                                           int row_a, int ks,
                                           uint32_t aF[8], uint32_t bF[16]) {
    const int k = ks * 8;
    #pragma unroll
    for (int mc = 0; mc < 2; mc++) {
        const float* Ar = A0 + (row_a + mc * 16) * KP + k;
        aF[mc * 4 + 0] = f2tf32(Ar[0]);
        aF[mc * 4 + 1] = f2tf32(Ar[8 * KP]);
        aF[mc * 4 + 2] = f2tf32(Ar[4]);
        aF[mc * 4 + 3] = f2tf32(Ar[8 * KP + 4]);
    }
    const uint32_t bks = bf_warp + (uint32_t)ks * 2048u;
    #pragma unroll
    for (int c = 0; c < 4; c++) {
        asm volatile("ld.shared.v4.b32 {%0,%1,%2,%3}, [%4];"
                     : "=r"(bF[c * 4 + 0]), "=r"(bF[c * 4 + 1]),
                       "=r"(bF[c * 4 + 2]), "=r"(bF[c * 4 + 3])
                     : "r"(bks + (uint32_t)c * 512u));
    }
}

__global__ void __launch_bounds__(NTHREADS, 1)
moe_mma_kernel(const float* __restrict__ X,
               const float* __restrict__ W,
               const void* __restrict__ expert_size,
               float* __restrict__ Y,
               long long total_tokens)
{
    extern __shared__ float smem[];
    float* Bf = smem;
    float* As = smem + BF_FLOATS;
    const uint32_t Bf_u32 = smem_u32(Bf);
    const uint32_t As_u32 = smem_u32(As);

    const int tid  = threadIdx.x;
    const int wid  = tid >> 5;
    const int lane = tid & 31;
    const int g    = lane >> 2;
    const int tig  = lane & 3;

    const int wm   = wid >> 1;              // 0..3
    const int wn   = wid & 1;               // 0..1

    const int e    = blockIdx.x / CPE;
    const int slot = blockIdx.x % CPE;

    const long long probe = reinterpret_cast<const long long*>(expert_size)[0];
    const bool is64 = (probe >= 0 && probe <= total_tokens);

    long long rb = 0;
    for (int i = 0; i < e; i++) rb += esz_get(expert_size, i, is64);
    long long esize = esz_get(expert_size, e, is64);
    if (rb < 0) rb = 0;
    if (rb > total_tokens) rb = total_tokens;
    if (esize < 0) esize = 0;
    if (rb + esize > total_tokens) esize = total_tokens - rb;

    const int etiles = (int)(esize / TM);
    const int q0 = etiles / CPE, r0c = etiles % CPE;
    const int tpc = q0 + (slot < r0c ? 1 : 0);
    const int t0  = slot * q0 + (slot < r0c ? slot : r0c);
    if (tpc == 0) return;

    // ---- Stage W_e into FRAGMENT-order SMEM (tf32 RN) ----
    {
        const float* wp = W + (size_t)e * ND * KD;
        for (int q = tid; q < 2 * 16 * 4 * 32; q += NTHREADS) {
            int l   = q & 31;
            int c   = (q >> 5) & 3;
            int vks = (q >> 7) & 15;
            int vwn = q >> 11;
            int vg = l >> 2, vtig = l & 3;
            int k  = vks * 8 + vtig;
            int n0 = vwn * 64 + (2 * c) * 8 + vg;
            int n1 = n0 + 8;
            uint32_t f0 = f2tf32(wp[n0 * KD + k]);
            uint32_t f1 = f2tf32(wp[n0 * KD + k + 4]);
            uint32_t f2 = f2tf32(wp[n1 * KD + k]);
            uint32_t f3 = f2tf32(wp[n1 * KD + k + 4]);
            uint32_t a = Bf_u32 + (uint32_t)q * 16u;
            asm volatile("st.shared.v4.b32 [%0], {%1,%2,%3,%4};"
                         :: "r"(a), "r"(f0), "r"(f1), "r"(f2), "r"(f3) : "memory");
        }
    }

    // ---- Prefetch first X tile into buffer 0 ----
    {
        const float4* xp = reinterpret_cast<const float4*>(X + (rb + (long long)t0 * TM) * KD);
        for (int q = tid; q < TM * KD / 4; q += NTHREADS) {
            int r = q >> 5, c4 = (q & 31) << 2;
            cp16(As_u32 + (uint32_t)(r * KP + c4) * 4u, xp + q);
        }
        asm volatile("cp.async.commit_group;" ::: "memory");
    }

    const int row_a = wm * 32 + g;
    const int colb0 = wn * 64;
    const uint32_t bf_warp = Bf_u32 + (uint32_t)(wn * 16) * 2048u + (uint32_t)lane * 16u;

    for (int it = 0; it < tpc; it++) {
        const int buf = it & 1;

        if (it + 1 < tpc) {
            const float4* xp = reinterpret_cast<const float4*>(
                X + (rb + (long long)(t0 + it + 1) * TM) * KD);
            uint32_t dbase = As_u32 + (uint32_t)((buf ^ 1) * TM * KP) * 4u;
            for (int q = tid; q < TM * KD / 4; q += NTHREADS) {
                int r = q >> 5, c4 = (q & 31) << 2;
                cp16(dbase + (uint32_t)(r * KP + c4) * 4u, xp + q);
            }
        }
        asm volatile("cp.async.commit_group;" ::: "memory");
        asm volatile("cp.async.wait_group 1;" ::: "memory");
        __syncthreads();

        // ---- Compute: warp-tile 32x64, register-double-buffered frags ----
        const float* A0 = As + buf * TM * KP;
        const float* A0t = A0 + tig;        // fold tig into base once

        float acc[16][4];
        #pragma unroll
        for (int p = 0; p < 16; p++)
            #pragma unroll
            for (int i = 0; i < 4; i++) acc[p][i] = 0.0f;

        uint32_t aF[2][8], bF[2][16];
        load_frags(A0t, bf_warp, row_a, 0, aF[0], bF[0]);

        #pragma unroll
        for (int ks = 0; ks < 16; ks++) {
            const int cur = ks & 1, nxt = cur ^ 1;
            if (ks < 15)
                load_frags(A0t, bf_warp, row_a, ks + 1, aF[nxt], bF[nxt]);
            #pragma unroll
            for (int mc = 0; mc < 2; mc++)
                #pragma unroll
                for (int nb = 0; nb < 8; nb++)
                    mma_tf32(acc[mc * 8 + nb],
                             aF[cur][mc * 4 + 0], aF[cur][mc * 4 + 1],
                             aF[cur][mc * 4 + 2], aF[cur][mc * 4 + 3],
                             bF[cur][nb * 2], bF[cur][nb * 2 + 1]);
        }

        // ---- Epilogue: st.global.v2 ----
        {
            const long long tile_row = rb + (long long)(t0 + it) * TM;
            #pragma unroll
            for (int mc = 0; mc < 2; mc++) {
                float* dst0 = Y + (tile_row + row_a + mc * 16)     * ND + colb0 + tig * 2;
                float* dst1 = Y + (tile_row + row_a + mc * 16 + 8) * ND + colb0 + tig * 2;
                #pragma unroll
                for (int nb = 0; nb < 8; nb++) {
                    float2 v0 = make_float2(acc[mc * 8 + nb][0], acc[mc * 8 + nb][1]);
                    float2 v1 = make_float2(acc[mc * 8 + nb][2], acc[mc * 8 + nb][3]);
                    *reinterpret_cast<float2*>(dst0 + nb * 8) = v0;
                    *reinterpret_cast<float2*>(dst1 + nb * 8) = v1;
                }
            }
        }
        __syncthreads();
    }
}

extern "C" void kernel_launch(void* const* d_in, const int* in_sizes, int n_in,
                              void* d_out, int out_size) {
    const float* X   = (const float*)d_in[0];
    const float* W   = (const float*)d_in[1];
    const void*  esz = d_in[2];
    float*       Y   = (float*)d_out;

    const long long total_tokens = (long long)in_sizes[0] / KD;

    cudaFuncSetAttribute(moe_mma_kernel,
                         cudaFuncAttributeMaxDynamicSharedMemorySize,
                         SMEM_FLOATS * (int)sizeof(float));

    moe_mma_kernel<<<NEXP * CPE, NTHREADS, SMEM_FLOATS * (int)sizeof(float)>>>(
        X, W, esz, Y, total_tokens);
}

// round 15
// speedup vs baseline: 1.7061x; 1.0523x over previous
#include <cuda_runtime.h>
#include <cstdint>

// ---------------------------------------------------------------------------
// MoE grouped GEMM: Y[t,o] = sum_k X[t,k] * W[e(t),o,k]
//   X: [1048576,128] f32, W: [16,128,128] f32, expert_size: [16] (i32/i64).
// mma.sync m16n8k8 tf32. 512 threads = 2 INDEPENDENT groups of 8 warps.
// Each group: own 64-row double-buffered X tiles (cp.async), own named
// barrier, interleaved tile set -> one group's mma phase overlaps the other
// group's epilogue/barrier/load-wait (R13/14 showed additive phases in a
// single lockstep pipeline). W in fragment-order SMEM, warp-tile 32x32.
// ---------------------------------------------------------------------------

#define TT   64           // tile rows per group-tile
#define KD   128
#define ND   128
#define KP   132          // padded A stride (floats), conflict-free
#define CPE  64           // CTAs per expert
#define NEXP 16
#define NTHREADS 512

// Bf: [4 wn4][16 ks][2 c][32 lane] float4 = 16384 floats (64 KB)
static constexpr int BF_FLOATS   = 4 * 16 * 2 * 32 * 4;
// A: 2 groups x 2 bufs x TT x KP = 33792 floats
static constexpr int SMEM_FLOATS = BF_FLOATS + 2 * 2 * TT * KP;   // 200704 B

__device__ __forceinline__ uint32_t smem_u32(const void* p) {
    uint32_t a;
    asm("{ .reg .u64 t; cvta.to.shared.u64 t, %1; cvt.u32.u64 %0, t; }" : "=r"(a) : "l"(p));
    return a;
}

__device__ __forceinline__ uint32_t f2tf32(float v) {
    uint32_t r;
    asm("cvt.rn.tf32.f32 %0, %1;" : "=r"(r) : "f"(v));
    return r;
}

__device__ __forceinline__ void cp16(uint32_t dst, const void* src) {
    asm volatile("cp.async.cg.shared.global [%0], [%1], 16;" :: "r"(dst), "l"(src));
}

__device__ __forceinline__ void mma_tf32(float c[4], uint32_t a0, uint32_t a1,
                                         uint32_t a2, uint32_t a3,
                                         uint32_t b0, uint32_t b1) {
    asm volatile(
        "mma.sync.aligned.m16n8k8.row.col.f32.tf32.tf32.f32 "
        "{%0,%1,%2,%3}, {%4,%5,%6,%7}, {%8,%9}, {%0,%1,%2,%3};"
        : "+f"(c[0]), "+f"(c[1]), "+f"(c[2]), "+f"(c[3])
        : "r"(a0), "r"(a1), "r"(a2), "r"(a3), "r"(b0), "r"(b1));
}

__device__ __forceinline__ long long esz_get(const void* esz, int i, bool is64) {
    if (is64) return reinterpret_cast<const long long*>(esz)[i];
    return (long long)reinterpret_cast<const int*>(esz)[i];
}

__global__ void __launch_bounds__(NTHREADS, 1)
moe_mma_kernel(const float* __restrict__ X,
               const float* __restrict__ W,
               const void* __restrict__ expert_size,
               float* __restrict__ Y,
               long long total_tokens)
{
    extern __shared__ float smem[];
    float* Bf = smem;
    float* As = smem + BF_FLOATS;
    const uint32_t Bf_u32 = smem_u32(Bf);

    const int tid  = threadIdx.x;
    const int wid  = tid >> 5;
    const int lane = tid & 31;
    const int g    = lane >> 2;
    const int tig  = lane & 3;

    const int gid  = wid >> 3;              // group 0 / 1
    const int gwid = wid & 7;               // warp within group
    const int gtid = tid & 255;             // thread within group
    const int wm   = gwid >> 2;             // 0..1 (32-row M half)
    const int wn4  = gwid & 3;              // 0..3 (32-col N quarter)

    // Group's A double buffer base
    float* Ag = As + gid * (2 * TT * KP);
    const uint32_t Ag_u32 = smem_u32(Ag);

    const int e    = blockIdx.x / CPE;
    const int slot = blockIdx.x % CPE;

    // expert_size dtype sniff (declared i64; JAX x64-off delivers i32).
    const long long probe = reinterpret_cast<const long long*>(expert_size)[0];
    const bool is64 = (probe >= 0 && probe <= total_tokens);

    long long rb = 0;
    for (int i = 0; i < e; i++) rb += esz_get(expert_size, i, is64);
    long long esize = esz_get(expert_size, e, is64);
    if (rb < 0) rb = 0;
    if (rb > total_tokens) rb = total_tokens;
    if (esize < 0) esize = 0;
    if (rb + esize > total_tokens) esize = total_tokens - rb;

    // Tiles are TT=64 rows. Partition across CTAs, then interleave by group.
    const int etiles = (int)(esize / TT);
    const int q0 = etiles / CPE, r0c = etiles % CPE;
    const int tpc = q0 + (slot < r0c ? 1 : 0);
    const int t0  = slot * q0 + (slot < r0c ? slot : r0c);
    const int gtpc = (tpc - gid + 1) >> 1;          // tiles for this group

    // ---- Stage W_e into FRAGMENT-order SMEM (tf32 RN), all 512 threads ----
    // Entry (vwn4, vks, c, l): float4 = {b0(nb=2c), b1(2c), b0(2c+1), b1(2c+1)}
    // with vg=l>>2, vtig=l&3, k=vks*8+vtig, n = vwn4*32 + nb*8 + vg,
    // b0 = W[n][k], b1 = W[n][k+4].
    if (tpc > 0) {
        const float* wp = W + (size_t)e * ND * KD;
        for (int q = tid; q < 4 * 16 * 2 * 32; q += NTHREADS) {
            int l    = q & 31;
            int c    = (q >> 5) & 1;
            int vks  = (q >> 6) & 15;
            int vwn4 = q >> 10;
            int vg = l >> 2, vtig = l & 3;
            int k  = vks * 8 + vtig;
            int n0 = vwn4 * 32 + (2 * c) * 8 + vg;
            int n1 = n0 + 8;
            uint32_t f0 = f2tf32(wp[n0 * KD + k]);
            uint32_t f1 = f2tf32(wp[n0 * KD + k + 4]);
            uint32_t f2 = f2tf32(wp[n1 * KD + k]);
            uint32_t f3 = f2tf32(wp[n1 * KD + k + 4]);
            uint32_t a = Bf_u32 + (uint32_t)q * 16u;
            asm volatile("st.shared.v4.b32 [%0], {%1,%2,%3,%4};"
                         :: "r"(a), "r"(f0), "r"(f1), "r"(f2), "r"(f3) : "memory");
        }
    }

    // ---- Group's first prefetch into its buffer 0 ----
    if (gtpc > 0) {
        const int tile0 = t0 + gid;
        const float4* xp = reinterpret_cast<const float4*>(X + (rb + (long long)tile0 * TT) * KD);
        for (int q = gtid; q < TT * KD / 4; q += 256) {
            int r = q >> 5, c4 = (q & 31) << 2;
            cp16(Ag_u32 + (uint32_t)(r * KP + c4) * 4u, xp + q);
        }
    }
    asm volatile("cp.async.commit_group;" ::: "memory");

    __syncthreads();                       // Bf visible to all; groups diverge now
    if (gtpc == 0) return;

    const int row_a = wm * 32 + g;         // first A row within group-tile
    const int colb0 = wn4 * 32;
    const uint32_t bf_warp = Bf_u32 + (uint32_t)wn4 * 16384u + (uint32_t)lane * 16u;
    const int bar_id = gid + 1;

    for (int it = 0; it < gtpc; it++) {
        const int buf = it & 1;
        const int tile = t0 + gid + 2 * it;

        // Prefetch this group's next tile into the other buffer.
        if (it + 1 < gtpc) {
            const int ntile = tile + 2;
            const float4* xp = reinterpret_cast<const float4*>(
                X + (rb + (long long)ntile * TT) * KD);
            uint32_t dbase = Ag_u32 + (uint32_t)((buf ^ 1) * TT * KP) * 4u;
            for (int q = gtid; q < TT * KD / 4; q += 256) {
                int r = q >> 5, c4 = (q & 31) << 2;
                cp16(dbase + (uint32_t)(r * KP + c4) * 4u, xp + q);
            }
        }
        asm volatile("cp.async.commit_group;" ::: "memory");
        asm volatile("cp.async.wait_group 1;" ::: "memory");
        asm volatile("bar.sync %0, 256;" :: "r"(bar_id) : "memory");

        // ---- Compute: warp-tile 32x32 ----
        const float* A0t = Ag + buf * TT * KP + tig;
        float acc[8][4];
        #pragma unroll
        for (int p = 0; p < 8; p++)
            #pragma unroll
            for (int i = 0; i < 4; i++) acc[p][i] = 0.0f;

        #pragma unroll
        for (int ks = 0; ks < 16; ks++) {
            const int k = ks * 8;
            uint32_t aF[8];
            #pragma unroll
            for (int mc = 0; mc < 2; mc++) {
                const float* Ar = A0t + (row_a + mc * 16) * KP + k;
                aF[mc * 4 + 0] = f2tf32(Ar[0]);
                aF[mc * 4 + 1] = f2tf32(Ar[8 * KP]);
                aF[mc * 4 + 2] = f2tf32(Ar[4]);
                aF[mc * 4 + 3] = f2tf32(Ar[8 * KP + 4]);
            }
            uint32_t bF[8];
            const uint32_t bks = bf_warp + (uint32_t)ks * 1024u;
            #pragma unroll
            for (int c = 0; c < 2; c++) {
                asm volatile("ld.shared.v4.b32 {%0,%1,%2,%3}, [%4];"
                             : "=r"(bF[c * 4 + 0]), "=r"(bF[c * 4 + 1]),
                               "=r"(bF[c * 4 + 2]), "=r"(bF[c * 4 + 3])
                             : "r"(bks + (uint32_t)c * 512u));
            }
            #pragma unroll
            for (int mc = 0; mc < 2; mc++)
                #pragma unroll
                for (int nb = 0; nb < 4; nb++) {
                    // v4 c=nb>>1 holds pairs for nb=2c (+0,+1) and nb=2c+1 (+2,+3)
                    const int bi = (nb >> 1) * 4 + (nb & 1) * 2;
                    mma_tf32(acc[mc * 4 + nb],
                             aF[mc * 4 + 0], aF[mc * 4 + 1],
                             aF[mc * 4 + 2], aF[mc * 4 + 3],
                             bF[bi], bF[bi + 1]);
                }
        }

        // ---- Epilogue: st.global.v2 (full 32B sectors) ----
        {
            const long long tile_row = rb + (long long)tile * TT;
            #pragma unroll
            for (int mc = 0; mc < 2; mc++) {
                float* dst0 = Y + (tile_row + row_a + mc * 16)     * ND + colb0 + tig * 2;
                float* dst1 = Y + (tile_row + row_a + mc * 16 + 8) * ND + colb0 + tig * 2;
                #pragma unroll
                for (int nb = 0; nb < 4; nb++) {
                    float2 v0 = make_float2(acc[mc * 4 + nb][0], acc[mc * 4 + nb][1]);
                    float2 v1 = make_float2(acc[mc * 4 + nb][2], acc[mc * 4 + nb][3]);
                    *reinterpret_cast<float2*>(dst0 + nb * 8) = v0;
                    *reinterpret_cast<float2*>(dst1 + nb * 8) = v1;
                }
            }
        }
        asm volatile("bar.sync %0, 256;" :: "r"(bar_id) : "memory");
    }
}

extern "C" void kernel_launch(void* const* d_in, const int* in_sizes, int n_in,
                              void* d_out, int out_size) {
    const float* X   = (const float*)d_in[0];
    const float* W   = (const float*)d_in[1];
    const void*  esz = d_in[2];
    float*       Y   = (float*)d_out;

    const long long total_tokens = (long long)in_sizes[0] / KD;

    cudaFuncSetAttribute(moe_mma_kernel,
                         cudaFuncAttributeMaxDynamicSharedMemorySize,
                         SMEM_FLOATS * (int)sizeof(float));

    moe_mma_kernel<<<NEXP * CPE, NTHREADS, SMEM_FLOATS * (int)sizeof(float)>>>(
        X, W, esz, Y, total_tokens);
}